// round 1
// baseline (speedup 1.0000x reference)
#include <cuda_runtime.h>
#include <math.h>

// Problem constants (fixed by the dataset)
#define T_DIM 512
#define B_DIM 64
#define E_DIM 300
#define H_DIM 800
#define L_DIM 3
#define M_DIM (T_DIM * B_DIM)      // 32768
#define N3H   (3 * H_DIM)          // 2400

// Static scratch (no allocations allowed)
__device__ float g_buf[(size_t)M_DIM * N3H];   // [T*B, 3H]  ~314 MB
__device__ float h_buf[(size_t)M_DIM * H_DIM]; // [T*B, H]   ~105 MB

// ---------------- Tiled SGEMM with bias: C[M,N] = A[M,K] * B[K,N] + bias[N] ----------------
#define BM 128
#define BN 128
#define BK 16
#define TM 8
#define TN 8

__global__ __launch_bounds__(256)
void sgemm_bias_kernel(const float* __restrict__ A, const float* __restrict__ B,
                       const float* __restrict__ bias, float* __restrict__ C,
                       int M, int N, int K) {
    __shared__ float As[BK][BM];
    __shared__ float Bs[BK][BN];

    const int tid = threadIdx.x;            // 0..255
    const int bm = blockIdx.y * BM;
    const int bn = blockIdx.x * BN;
    const int tm = (tid / 16) * TM;          // 16x16 thread grid
    const int tn = (tid % 16) * TN;

    float acc[TM][TN];
#pragma unroll
    for (int i = 0; i < TM; i++)
#pragma unroll
        for (int j = 0; j < TN; j++) acc[i][j] = 0.f;

    for (int k0 = 0; k0 < K; k0 += BK) {
        // Load A tile (BM x BK), store transposed As[k][m]
#pragma unroll
        for (int i = 0; i < (BM * BK) / 256; i++) {
            int idx = tid + i * 256;
            int r = idx / BK, c = idx % BK;
            int gr = bm + r, gc = k0 + c;
            As[c][r] = (gr < M && gc < K) ? A[(long)gr * K + gc] : 0.f;
        }
        // Load B tile (BK x BN)
#pragma unroll
        for (int i = 0; i < (BK * BN) / 256; i++) {
            int idx = tid + i * 256;
            int r = idx / BN, c = idx % BN;
            int gr = k0 + r, gc = bn + c;
            Bs[r][c] = (gr < K && gc < N) ? B[(long)gr * N + gc] : 0.f;
        }
        __syncthreads();

#pragma unroll
        for (int k = 0; k < BK; k++) {
            float ar[TM], br[TN];
#pragma unroll
            for (int i = 0; i < TM; i++) ar[i] = As[k][tm + i];
#pragma unroll
            for (int j = 0; j < TN; j++) br[j] = Bs[k][tn + j];
#pragma unroll
            for (int i = 0; i < TM; i++)
#pragma unroll
                for (int j = 0; j < TN; j++) acc[i][j] += ar[i] * br[j];
        }
        __syncthreads();
    }

#pragma unroll
    for (int i = 0; i < TM; i++) {
        int gr = bm + tm + i;
        if (gr >= M) continue;
#pragma unroll
        for (int j = 0; j < TN; j++) {
            int gc = bn + tn + j;
            if (gc < N) C[(long)gr * N + gc] = acc[i][j] + bias[gc];
        }
    }
}

// ---------------- fo-pool scan: per (b, j) lane, sequential over T ----------------
// g: [T, B, 3H] (z | f | o).  h: [T, B, H].  out: [B, L*H], write layer's final c.
__global__ __launch_bounds__(256)
void fo_pool_scan_kernel(const float* __restrict__ g, float* __restrict__ h,
                         float* __restrict__ out, int layer) {
    int idx = blockIdx.x * blockDim.x + threadIdx.x;
    if (idx >= B_DIM * H_DIM) return;
    int b = idx / H_DIM;
    int j = idx % H_DIM;

    float c = 0.f;
    const long row_base = (long)b * N3H + j;
    const long h_base = (long)b * H_DIM + j;
    for (int t = 0; t < T_DIM; t++) {
        long base = (long)t * B_DIM * N3H + row_base;
        float z = g[base];
        float f = g[base + H_DIM];
        float o = g[base + 2 * H_DIM];
        float fs = 1.f / (1.f + expf(-f));
        float zt = tanhf(z);
        c = fs * zt + (1.f - fs) * c;
        float os = 1.f / (1.f + expf(-o));
        h[(long)t * B_DIM * H_DIM + h_base] = os * c;
    }
    out[(long)b * (L_DIM * H_DIM) + (long)layer * H_DIM + j] = c;
}

extern "C" void kernel_launch(void* const* d_in, const int* in_sizes, int n_in,
                              void* d_out, int out_size) {
    const float* sent = (const float*)d_in[0];
    // d_in[1] = lengths (unused by reference)
    const float* W0 = (const float*)d_in[2];
    const float* b0 = (const float*)d_in[3];
    const float* W1 = (const float*)d_in[4];
    const float* b1 = (const float*)d_in[5];
    const float* W2 = (const float*)d_in[6];
    const float* b2 = (const float*)d_in[7];
    float* out = (float*)d_out;

    float* g;
    float* h;
    cudaGetSymbolAddress((void**)&g, g_buf);
    cudaGetSymbolAddress((void**)&h, h_buf);

    dim3 gemm_grid((N3H + BN - 1) / BN, (M_DIM + BM - 1) / BM);
    dim3 gemm_blk(256);
    int scan_threads = 256;
    int scan_blocks = (B_DIM * H_DIM + scan_threads - 1) / scan_threads;

    // Layer 0: input = sent [M, E]
    sgemm_bias_kernel<<<gemm_grid, gemm_blk>>>(sent, W0, b0, g, M_DIM, N3H, E_DIM);
    fo_pool_scan_kernel<<<scan_blocks, scan_threads>>>(g, h, out, 0);

    // Layer 1: input = h [M, H]
    sgemm_bias_kernel<<<gemm_grid, gemm_blk>>>(h, W1, b1, g, M_DIM, N3H, H_DIM);
    fo_pool_scan_kernel<<<scan_blocks, scan_threads>>>(g, h, out, 1);

    // Layer 2
    sgemm_bias_kernel<<<gemm_grid, gemm_blk>>>(h, W2, b2, g, M_DIM, N3H, H_DIM);
    fo_pool_scan_kernel<<<scan_blocks, scan_threads>>>(g, h, out, 2);
}

// round 3
// speedup vs baseline: 2.8920x; 2.8920x over previous
#include <cuda_runtime.h>
#include <cuda_bf16.h>
#include <cstdint>
#include <math.h>

// ---------------- problem constants ----------------
#define T_DIM 512
#define B_DIM 64
#define E_DIM 300
#define H_DIM 800
#define L_DIM 3
#define M_DIM (T_DIM * B_DIM)   // 32768
#define N_OUT 2400              // 3*H
#define N_PADROWS 2432          // N padded to mult of 128 (B-operand rows)
#define KPAD0 320               // 300 -> mult of 32
#define KPAD  832               // 800 -> mult of 32

// GEMM tiling
#define BM 128
#define BN 128
#define BK 32
#define STAGES 3
#define STAGE_BYTES 32768
#define AH_OFF 0
#define AL_OFF 8192
#define BH_OFF 16384
#define BL_OFF 24576

// ---------------- static scratch ----------------
__device__ float g_buf[(size_t)M_DIM * N_OUT];                 // activations zt|fs|os
__device__ __nv_bfloat16 A0h[(size_t)M_DIM * KPAD0];
__device__ __nv_bfloat16 A0l[(size_t)M_DIM * KPAD0];
__device__ __nv_bfloat16 A12h[(size_t)M_DIM * KPAD];
__device__ __nv_bfloat16 A12l[(size_t)M_DIM * KPAD];
__device__ __nv_bfloat16 W0h_buf[(size_t)N_PADROWS * KPAD0];
__device__ __nv_bfloat16 W0l_buf[(size_t)N_PADROWS * KPAD0];
__device__ __nv_bfloat16 W1h_buf[(size_t)N_PADROWS * KPAD];
__device__ __nv_bfloat16 W1l_buf[(size_t)N_PADROWS * KPAD];
__device__ __nv_bfloat16 W2h_buf[(size_t)N_PADROWS * KPAD];
__device__ __nv_bfloat16 W2l_buf[(size_t)N_PADROWS * KPAD];

// ---------------- helpers ----------------
__device__ __forceinline__ uint32_t smem_u32(const void* p) {
    uint32_t a;
    asm("{ .reg .u64 t; cvta.to.shared.u64 t, %1; cvt.u32.u64 %0, t; }" : "=r"(a) : "l"(p));
    return a;
}
__device__ __forceinline__ void cp16(uint32_t dst, const void* src) {
    asm volatile("cp.async.cg.shared.global [%0], [%1], 16;" :: "r"(dst), "l"(src) : "memory");
}
__device__ __forceinline__ void cp_commit() {
    asm volatile("cp.async.commit_group;" ::: "memory");
}
template <int N> __device__ __forceinline__ void cp_wait() {
    asm volatile("cp.async.wait_group %0;" :: "n"(N) : "memory");
}
__device__ __forceinline__ void ldsm4(uint32_t& r0, uint32_t& r1, uint32_t& r2, uint32_t& r3,
                                      uint32_t addr) {
    asm volatile("ldmatrix.sync.aligned.m8n8.x4.shared.b16 {%0,%1,%2,%3}, [%4];"
                 : "=r"(r0), "=r"(r1), "=r"(r2), "=r"(r3) : "r"(addr));
}
__device__ __forceinline__ void mma_bf16(float* c, const uint32_t* a, const uint32_t* b) {
    asm volatile(
        "mma.sync.aligned.m16n8k16.row.col.f32.bf16.bf16.f32 "
        "{%0,%1,%2,%3}, {%4,%5,%6,%7}, {%8,%9}, {%0,%1,%2,%3};"
        : "+f"(c[0]), "+f"(c[1]), "+f"(c[2]), "+f"(c[3])
        : "r"(a[0]), "r"(a[1]), "r"(a[2]), "r"(a[3]), "r"(b[0]), "r"(b[1]));
}
__device__ __forceinline__ float sigmoidf_(float x) { return 1.f / (1.f + __expf(-x)); }
__device__ __forceinline__ float tanhf_(float x)    { return 1.f - 2.f / (__expf(2.f * x) + 1.f); }

// ---------------- weight transpose + bf16 split: W[K,N] -> Wt[Np,Kp] hi/lo ----------------
__global__ void conv_w_kernel(const float* __restrict__ W,
                              __nv_bfloat16* __restrict__ Th, __nv_bfloat16* __restrict__ Tl,
                              int K, int Kp) {
    __shared__ float tile[32][33];
    int kb = blockIdx.y * 32, nb = blockIdx.x * 32;
    for (int r = threadIdx.y; r < 32; r += 8) {
        int k = kb + r, n = nb + threadIdx.x;
        tile[r][threadIdx.x] = (k < K && n < N_OUT) ? W[(size_t)k * N_OUT + n] : 0.f;
    }
    __syncthreads();
    for (int r = threadIdx.y; r < 32; r += 8) {
        int n = nb + r, k = kb + threadIdx.x;
        float v = tile[threadIdx.x][r];
        __nv_bfloat16 hi = __float2bfloat16(v);
        Th[(size_t)n * Kp + k] = hi;
        Tl[(size_t)n * Kp + k] = __float2bfloat16(v - __bfloat162float(hi));
    }
}

// ---------------- sent fp32 -> bf16 hi/lo (padded K) ----------------
__global__ void conv_sent_kernel(const float* __restrict__ x) {
    size_t i = (size_t)blockIdx.x * 256 + threadIdx.x;
    if (i >= (size_t)M_DIM * KPAD0) return;
    size_t row = i / KPAD0;
    int j = (int)(i % KPAD0);
    float v = (j < E_DIM) ? x[row * E_DIM + j] : 0.f;
    __nv_bfloat16 hi = __float2bfloat16(v);
    A0h[i] = hi;
    A0l[i] = __float2bfloat16(v - __bfloat162float(hi));
}

// ---------------- bf16x3 HMMA GEMM with fused bias + activation ----------------
// C[m, n] = act( sum_k A[m,k] * Wt[n,k] + bias[n] ), act = tanh (n<H) else sigmoid
__global__ __launch_bounds__(256)
void qrnn_gemm_kernel(const __nv_bfloat16* __restrict__ Ah, const __nv_bfloat16* __restrict__ Al,
                      const __nv_bfloat16* __restrict__ Bh, const __nv_bfloat16* __restrict__ Bl,
                      int ldk, int nc,
                      const float* __restrict__ bias, float* __restrict__ C) {
    extern __shared__ char smem[];
    const uint32_t sbase = smem_u32(smem);

    const int tid = threadIdx.x;
    const int lane = tid & 31;
    const int wid = tid >> 5;
    const int wm = wid >> 2;          // 0..1 -> 64-row slabs
    const int wn = wid & 3;           // 0..3 -> 32-col slabs
    const int am0 = blockIdx.y * BM;
    const int bn0 = blockIdx.x * BN;

    // ---- stage loader: 8 x cp.async(16B) per thread ----
    auto load_stage = [&](int kc, int st) {
        const size_t kof = (size_t)kc * BK;
        uint32_t sb = sbase + st * STAGE_BYTES;
#pragma unroll
        for (int i = 0; i < 2; i++) {
            int id = tid + i * 256;        // 0..511
            int row = id >> 2, c = id & 3;
            int sc = c ^ ((row >> 1) & 3);
            uint32_t soff = row * 64 + sc * 16;
            size_t ga = (size_t)(am0 + row) * ldk + kof + (size_t)c * 8;
            size_t gb = (size_t)(bn0 + row) * ldk + kof + (size_t)c * 8;
            cp16(sb + AH_OFF + soff, Ah + ga);
            cp16(sb + AL_OFF + soff, Al + ga);
            cp16(sb + BH_OFF + soff, Bh + gb);
            cp16(sb + BL_OFF + soff, Bl + gb);
        }
    };

    float acc[4][4][4];
#pragma unroll
    for (int i = 0; i < 4; i++)
#pragma unroll
        for (int j = 0; j < 4; j++)
#pragma unroll
            for (int q = 0; q < 4; q++) acc[i][j][q] = 0.f;

    load_stage(0, 0); cp_commit();
    if (nc > 1) { load_stage(1, 1); cp_commit(); }

    const int lr = lane & 15;
    const int lc = lane >> 4;

    for (int kc = 0; kc < nc; kc++) {
        if (kc + 1 < nc) cp_wait<1>(); else cp_wait<0>();
        __syncthreads();
        if (kc + 2 < nc) { load_stage(kc + 2, (kc + 2) % STAGES); cp_commit(); }

        uint32_t sb = sbase + (kc % STAGES) * STAGE_BYTES;
#pragma unroll
        for (int kk = 0; kk < 2; kk++) {
            // B fragments for this k-half: 4 n8-groups, hi+lo
            uint32_t bh[4][2], bl[4][2];
#pragma unroll
            for (int p = 0; p < 2; p++) {
                int rowb = wn * 32 + p * 16 + lr;
                uint32_t off = rowb * 64 + (((kk * 2 + lc) ^ ((rowb >> 1) & 3)) * 16);
                uint32_t r0, r1, r2, r3;
                ldsm4(r0, r1, r2, r3, sb + BH_OFF + off);
                bh[2 * p][0] = r0; bh[2 * p + 1][0] = r1;
                bh[2 * p][1] = r2; bh[2 * p + 1][1] = r3;
                ldsm4(r0, r1, r2, r3, sb + BL_OFF + off);
                bl[2 * p][0] = r0; bl[2 * p + 1][0] = r1;
                bl[2 * p][1] = r2; bl[2 * p + 1][1] = r3;
            }
#pragma unroll
            for (int mt = 0; mt < 4; mt++) {
                int rowa = wm * 64 + mt * 16 + lr;
                uint32_t off = rowa * 64 + (((kk * 2 + lc) ^ ((rowa >> 1) & 3)) * 16);
                uint32_t ah[4], al[4];
                ldsm4(ah[0], ah[1], ah[2], ah[3], sb + AH_OFF + off);
                ldsm4(al[0], al[1], al[2], al[3], sb + AL_OFF + off);
#pragma unroll
                for (int ng = 0; ng < 4; ng++) {
                    mma_bf16(acc[mt][ng], ah, bh[ng]);
                    mma_bf16(acc[mt][ng], ah, bl[ng]);
                    mma_bf16(acc[mt][ng], al, bh[ng]);
                }
            }
        }
        __syncthreads();
    }

    // ---- epilogue: bias + activation, direct 8B stores ----
    const int tg = lane >> 2;          // row within tile
    const int tq = lane & 3;           // col pair
#pragma unroll
    for (int ng = 0; ng < 4; ng++) {
        int colb = bn0 + wn * 32 + ng * 8;
        if (colb >= N_OUT) continue;
        int col = colb + tq * 2;
        float2 bv = *reinterpret_cast<const float2*>(&bias[col]);
        bool is_t = colb < H_DIM;
#pragma unroll
        for (int mt = 0; mt < 4; mt++) {
            int r0 = am0 + wm * 64 + mt * 16 + tg;
            float x0 = acc[mt][ng][0] + bv.x;
            float x1 = acc[mt][ng][1] + bv.y;
            float x2 = acc[mt][ng][2] + bv.x;
            float x3 = acc[mt][ng][3] + bv.y;
            float2 v0, v1;
            v0.x = is_t ? tanhf_(x0) : sigmoidf_(x0);
            v0.y = is_t ? tanhf_(x1) : sigmoidf_(x1);
            v1.x = is_t ? tanhf_(x2) : sigmoidf_(x2);
            v1.y = is_t ? tanhf_(x3) : sigmoidf_(x3);
            *reinterpret_cast<float2*>(&C[(size_t)r0 * N_OUT + col]) = v0;
            *reinterpret_cast<float2*>(&C[(size_t)(r0 + 8) * N_OUT + col]) = v1;
        }
    }
}

// ---------------- fo-pool scan: pre-activated g -> h (bf16 hi/lo) + final c ----------------
__global__ __launch_bounds__(256)
void qrnn_scan_kernel(const float* __restrict__ g,
                      __nv_bfloat16* __restrict__ Hh, __nv_bfloat16* __restrict__ Hl,
                      float* __restrict__ out, int layer, int write_h) {
    int idx = blockIdx.x * 256 + threadIdx.x;
    if (idx >= B_DIM * KPAD) return;
    int b = idx / KPAD;
    int j = idx % KPAD;

    if (j >= H_DIM) {  // zero the K padding of the next layer's A operand
        if (write_h) {
            __nv_bfloat16 z = __float2bfloat16(0.f);
            for (int t = 0; t < T_DIM; t++) {
                size_t o = (size_t)(t * B_DIM + b) * KPAD + j;
                Hh[o] = z; Hl[o] = z;
            }
        }
        return;
    }

    const float* gp = g + (size_t)b * N_OUT + j;
    float c = 0.f;
    for (int t0 = 0; t0 < T_DIM; t0 += 4) {
        float zt[4], fs[4], os[4];
#pragma unroll
        for (int u = 0; u < 4; u++) {
            size_t base = (size_t)(t0 + u) * B_DIM * N_OUT;
            zt[u] = gp[base];
            fs[u] = gp[base + H_DIM];
            os[u] = gp[base + 2 * H_DIM];
        }
#pragma unroll
        for (int u = 0; u < 4; u++) {
            c = fmaf(fs[u], zt[u] - c, c);       // fs*zt + (1-fs)*c
            if (write_h) {
                float h = os[u] * c;
                __nv_bfloat16 hi = __float2bfloat16(h);
                size_t o = (size_t)((t0 + u) * B_DIM + b) * KPAD + j;
                Hh[o] = hi;
                Hl[o] = __float2bfloat16(h - __bfloat162float(hi));
            }
        }
    }
    out[(size_t)b * (L_DIM * H_DIM) + (size_t)layer * H_DIM + j] = c;
}

// ---------------- launch ----------------
extern "C" void kernel_launch(void* const* d_in, const int* in_sizes, int n_in,
                              void* d_out, int out_size) {
    const float* sent = (const float*)d_in[0];
    const float* W0 = (const float*)d_in[2];
    const float* b0 = (const float*)d_in[3];
    const float* W1 = (const float*)d_in[4];
    const float* b1 = (const float*)d_in[5];
    const float* W2 = (const float*)d_in[6];
    const float* b2 = (const float*)d_in[7];
    float* out = (float*)d_out;

    float* g;        cudaGetSymbolAddress((void**)&g, g_buf);
    __nv_bfloat16 *a0h, *a0l, *a12h, *a12l, *w0h, *w0l, *w1h, *w1l, *w2h, *w2l;
    cudaGetSymbolAddress((void**)&a0h, A0h);   cudaGetSymbolAddress((void**)&a0l, A0l);
    cudaGetSymbolAddress((void**)&a12h, A12h); cudaGetSymbolAddress((void**)&a12l, A12l);
    cudaGetSymbolAddress((void**)&w0h, W0h_buf); cudaGetSymbolAddress((void**)&w0l, W0l_buf);
    cudaGetSymbolAddress((void**)&w1h, W1h_buf); cudaGetSymbolAddress((void**)&w1l, W1l_buf);
    cudaGetSymbolAddress((void**)&w2h, W2h_buf); cudaGetSymbolAddress((void**)&w2l, W2l_buf);

    cudaFuncSetAttribute(qrnn_gemm_kernel, cudaFuncAttributeMaxDynamicSharedMemorySize,
                         STAGES * STAGE_BYTES);

    dim3 wblk(32, 8);
    dim3 wgrid0(N_PADROWS / 32, KPAD0 / 32);
    dim3 wgrid12(N_PADROWS / 32, KPAD / 32);
    conv_w_kernel<<<wgrid0, wblk>>>(W0, w0h, w0l, E_DIM, KPAD0);
    conv_w_kernel<<<wgrid12, wblk>>>(W1, w1h, w1l, H_DIM, KPAD);
    conv_w_kernel<<<wgrid12, wblk>>>(W2, w2h, w2l, H_DIM, KPAD);

    {
        size_t n = (size_t)M_DIM * KPAD0;
        conv_sent_kernel<<<(unsigned)((n + 255) / 256), 256>>>(sent);
    }

    dim3 ggrid(N_PADROWS / BN, M_DIM / BM);   // (19, 256)
    int scan_blocks = (B_DIM * KPAD + 255) / 256;
    size_t smem = STAGES * STAGE_BYTES;

    qrnn_gemm_kernel<<<ggrid, 256, smem>>>(a0h, a0l, w0h, w0l, KPAD0, KPAD0 / BK, b0, g);
    qrnn_scan_kernel<<<scan_blocks, 256>>>(g, a12h, a12l, out, 0, 1);

    qrnn_gemm_kernel<<<ggrid, 256, smem>>>(a12h, a12l, w1h, w1l, KPAD, KPAD / BK, b1, g);
    qrnn_scan_kernel<<<scan_blocks, 256>>>(g, a12h, a12l, out, 1, 1);

    qrnn_gemm_kernel<<<ggrid, 256, smem>>>(a12h, a12l, w2h, w2l, KPAD, KPAD / BK, b2, g);
    qrnn_scan_kernel<<<scan_blocks, 256>>>(g, a12h, a12l, out, 2, 0);
}

// round 4
// speedup vs baseline: 5.9794x; 2.0675x over previous
#include <cuda_runtime.h>
#include <cuda_fp16.h>
#include <cstdint>
#include <math.h>

// ---------------- problem constants ----------------
#define T_DIM 512
#define B_DIM 64
#define E_DIM 300
#define H_DIM 800
#define L_DIM 3
#define M_DIM (T_DIM * B_DIM)   // 32768
#define N_OUT 2400              // 3*H
#define N_PADROWS 2432          // N padded to mult of 128
#define KPAD0 320               // 300 -> mult of 32
#define KPAD  832               // 800 -> mult of 32

// scan chunking
#define NCH 8
#define TC  (T_DIM / NCH)       // 64

// GEMM tiling
#define BM 128
#define BN 128
#define BK 32
#define STAGES 3
#define STAGE_BYTES 24576
#define A_OFF  0
#define BH_OFF 8192
#define BL_OFF 16384
#define WSCALE 32.0f
#define INV_WSCALE (1.0f / 32.0f)

// ---------------- static scratch ----------------
__device__ float g_buf[(size_t)M_DIM * N_OUT];            // pre-activated z|f|o (post-act actually)
__device__ __half A0_buf[(size_t)M_DIM * KPAD0];          // layer0 A operand
__device__ __half A12_buf[(size_t)M_DIM * KPAD];          // layers 1/2 A operand (h)
__device__ __half W0h_buf[(size_t)N_PADROWS * KPAD0];
__device__ __half W0l_buf[(size_t)N_PADROWS * KPAD0];
__device__ __half W1h_buf[(size_t)N_PADROWS * KPAD];
__device__ __half W1l_buf[(size_t)N_PADROWS * KPAD];
__device__ __half W2h_buf[(size_t)N_PADROWS * KPAD];
__device__ __half W2l_buf[(size_t)N_PADROWS * KPAD];
__device__ float Pc_buf[(size_t)NCH * B_DIM * H_DIM];     // per-chunk product of (1-f)
__device__ float Cc_buf[(size_t)NCH * B_DIM * H_DIM];     // per-chunk local final c

// ---------------- helpers ----------------
__device__ __forceinline__ uint32_t smem_u32(const void* p) {
    uint32_t a;
    asm("{ .reg .u64 t; cvta.to.shared.u64 t, %1; cvt.u32.u64 %0, t; }" : "=r"(a) : "l"(p));
    return a;
}
__device__ __forceinline__ void cp16(uint32_t dst, const void* src) {
    asm volatile("cp.async.cg.shared.global [%0], [%1], 16;" :: "r"(dst), "l"(src) : "memory");
}
__device__ __forceinline__ void cp_commit() {
    asm volatile("cp.async.commit_group;" ::: "memory");
}
template <int N> __device__ __forceinline__ void cp_wait() {
    asm volatile("cp.async.wait_group %0;" :: "n"(N) : "memory");
}
__device__ __forceinline__ void ldsm4(uint32_t& r0, uint32_t& r1, uint32_t& r2, uint32_t& r3,
                                      uint32_t addr) {
    asm volatile("ldmatrix.sync.aligned.m8n8.x4.shared.b16 {%0,%1,%2,%3}, [%4];"
                 : "=r"(r0), "=r"(r1), "=r"(r2), "=r"(r3) : "r"(addr));
}
__device__ __forceinline__ void mma_f16(float* c, const uint32_t* a, const uint32_t* b) {
    asm volatile(
        "mma.sync.aligned.m16n8k16.row.col.f32.f16.f16.f32 "
        "{%0,%1,%2,%3}, {%4,%5,%6,%7}, {%8,%9}, {%0,%1,%2,%3};"
        : "+f"(c[0]), "+f"(c[1]), "+f"(c[2]), "+f"(c[3])
        : "r"(a[0]), "r"(a[1]), "r"(a[2]), "r"(a[3]), "r"(b[0]), "r"(b[1]));
}
__device__ __forceinline__ float sigmoidf_(float x) { return 1.f / (1.f + __expf(-x)); }
__device__ __forceinline__ float tanhf_(float x)    { return 1.f - 2.f / (__expf(2.f * x) + 1.f); }

// ---------------- weight transpose + fp16 split (scaled x32): W[K,N] -> Wt[Np,Kp] hi/lo ----
__global__ void conv_w_kernel(const float* __restrict__ W,
                              __half* __restrict__ Th, __half* __restrict__ Tl,
                              int K, int Kp) {
    __shared__ float tile[32][33];
    int kb = blockIdx.y * 32, nb = blockIdx.x * 32;
    for (int r = threadIdx.y; r < 32; r += 8) {
        int k = kb + r, n = nb + threadIdx.x;
        tile[r][threadIdx.x] = (k < K && n < N_OUT) ? W[(size_t)k * N_OUT + n] : 0.f;
    }
    __syncthreads();
    for (int r = threadIdx.y; r < 32; r += 8) {
        int n = nb + r, k = kb + threadIdx.x;
        float v = tile[threadIdx.x][r] * WSCALE;
        __half hi = __float2half(v);
        Th[(size_t)n * Kp + k] = hi;
        Tl[(size_t)n * Kp + k] = __float2half(v - __half2float(hi));
    }
}

// ---------------- sent fp32 -> fp16 (padded K) ----------------
__global__ void conv_sent_kernel(const float* __restrict__ x) {
    size_t i = (size_t)blockIdx.x * 256 + threadIdx.x;
    if (i >= (size_t)M_DIM * KPAD0) return;
    size_t row = i / KPAD0;
    int j = (int)(i % KPAD0);
    A0_buf[i] = __float2half((j < E_DIM) ? x[row * E_DIM + j] : 0.f);
}

// ---------------- fp16x2 HMMA GEMM with fused bias + activation ----------------
// g[m,n] = act( (1/32) * sum_k A[m,k]*(Wh+Wl)[n,k] + bias[n] )
__global__ __launch_bounds__(256, 2)
void qrnn_gemm_kernel(const __half* __restrict__ A,
                      const __half* __restrict__ Bh, const __half* __restrict__ Bl,
                      int ldk, int nc,
                      const float* __restrict__ bias, float* __restrict__ C) {
    extern __shared__ char smem[];
    const uint32_t sbase = smem_u32(smem);

    const int tid = threadIdx.x;
    const int lane = tid & 31;
    const int wid = tid >> 5;
    const int wm = wid >> 2;          // 0..1 -> 64-row slabs
    const int wn = wid & 3;           // 0..3 -> 32-col slabs
    const int am0 = blockIdx.y * BM;
    const int bn0 = blockIdx.x * BN;

    auto load_stage = [&](int kc, int st) {
        const size_t kof = (size_t)kc * BK;
        uint32_t sb = sbase + st * STAGE_BYTES;
#pragma unroll
        for (int i = 0; i < 2; i++) {
            int id = tid + i * 256;        // 0..511
            int row = id >> 2, c = id & 3;
            int sc = c ^ ((row >> 1) & 3);
            uint32_t soff = row * 64 + sc * 16;
            size_t ga = (size_t)(am0 + row) * ldk + kof + (size_t)c * 8;
            size_t gb = (size_t)(bn0 + row) * ldk + kof + (size_t)c * 8;
            cp16(sb + A_OFF + soff, A + ga);
            cp16(sb + BH_OFF + soff, Bh + gb);
            cp16(sb + BL_OFF + soff, Bl + gb);
        }
    };

    float acc[4][4][4];
#pragma unroll
    for (int i = 0; i < 4; i++)
#pragma unroll
        for (int j = 0; j < 4; j++)
#pragma unroll
            for (int q = 0; q < 4; q++) acc[i][j][q] = 0.f;

    load_stage(0, 0); cp_commit();
    if (nc > 1) { load_stage(1, 1); cp_commit(); }

    const int lr = lane & 15;
    const int lc = lane >> 4;

    for (int kc = 0; kc < nc; kc++) {
        if (kc + 1 < nc) cp_wait<1>(); else cp_wait<0>();
        __syncthreads();
        if (kc + 2 < nc) { load_stage(kc + 2, (kc + 2) % STAGES); cp_commit(); }

        uint32_t sb = sbase + (kc % STAGES) * STAGE_BYTES;
#pragma unroll
        for (int kk = 0; kk < 2; kk++) {
            uint32_t bh[4][2], bl[4][2];
#pragma unroll
            for (int p = 0; p < 2; p++) {
                int rowb = wn * 32 + p * 16 + lr;
                uint32_t off = rowb * 64 + (((kk * 2 + lc) ^ ((rowb >> 1) & 3)) * 16);
                uint32_t r0, r1, r2, r3;
                ldsm4(r0, r1, r2, r3, sb + BH_OFF + off);
                bh[2 * p][0] = r0; bh[2 * p + 1][0] = r1;
                bh[2 * p][1] = r2; bh[2 * p + 1][1] = r3;
                ldsm4(r0, r1, r2, r3, sb + BL_OFF + off);
                bl[2 * p][0] = r0; bl[2 * p + 1][0] = r1;
                bl[2 * p][1] = r2; bl[2 * p + 1][1] = r3;
            }
#pragma unroll
            for (int mt = 0; mt < 4; mt++) {
                int rowa = wm * 64 + mt * 16 + lr;
                uint32_t off = rowa * 64 + (((kk * 2 + lc) ^ ((rowa >> 1) & 3)) * 16);
                uint32_t a[4];
                ldsm4(a[0], a[1], a[2], a[3], sb + A_OFF + off);
#pragma unroll
                for (int ng = 0; ng < 4; ng++) {
                    mma_f16(acc[mt][ng], a, bh[ng]);
                    mma_f16(acc[mt][ng], a, bl[ng]);
                }
            }
        }
        __syncthreads();
    }

    // ---- epilogue: unscale + bias + activation, 8B stores ----
    const int tg = lane >> 2;
    const int tq = lane & 3;
#pragma unroll
    for (int ng = 0; ng < 4; ng++) {
        int colb = bn0 + wn * 32 + ng * 8;
        if (colb >= N_OUT) continue;
        int col = colb + tq * 2;
        float2 bv = *reinterpret_cast<const float2*>(&bias[col]);
        bool is_t = colb < H_DIM;
#pragma unroll
        for (int mt = 0; mt < 4; mt++) {
            int r0 = am0 + wm * 64 + mt * 16 + tg;
            float x0 = acc[mt][ng][0] * INV_WSCALE + bv.x;
            float x1 = acc[mt][ng][1] * INV_WSCALE + bv.y;
            float x2 = acc[mt][ng][2] * INV_WSCALE + bv.x;
            float x3 = acc[mt][ng][3] * INV_WSCALE + bv.y;
            float2 v0, v1;
            v0.x = is_t ? tanhf_(x0) : sigmoidf_(x0);
            v0.y = is_t ? tanhf_(x1) : sigmoidf_(x1);
            v1.x = is_t ? tanhf_(x2) : sigmoidf_(x2);
            v1.y = is_t ? tanhf_(x3) : sigmoidf_(x3);
            *reinterpret_cast<float2*>(&C[(size_t)r0 * N_OUT + col]) = v0;
            *reinterpret_cast<float2*>(&C[(size_t)(r0 + 8) * N_OUT + col]) = v1;
        }
    }
}

// ---------------- scan phase 1: per-chunk (prod(1-f), local c) ----------------
__global__ __launch_bounds__(256)
void scan_phase1_kernel(const float* __restrict__ g) {
    int idx = blockIdx.x * 256 + threadIdx.x;
    if (idx >= NCH * B_DIM * H_DIM) return;
    int j = idx % H_DIM;
    int b = (idx / H_DIM) % B_DIM;
    int ch = idx / (H_DIM * B_DIM);

    const float* gp = g + (size_t)b * N_OUT + j;
    float c = 0.f, P = 1.f;
    int t0b = ch * TC;
    for (int t0 = t0b; t0 < t0b + TC; t0 += 4) {
        float zt[4], fs[4];
#pragma unroll
        for (int u = 0; u < 4; u++) {
            size_t base = (size_t)(t0 + u) * B_DIM * N_OUT;
            zt[u] = gp[base];
            fs[u] = gp[base + H_DIM];
        }
#pragma unroll
        for (int u = 0; u < 4; u++) {
            c = fmaf(fs[u], zt[u] - c, c);
            P *= (1.f - fs[u]);
        }
    }
    Pc_buf[idx] = P;
    Cc_buf[idx] = c;
}

// ---------------- scan phase 2: prefix + re-scan, write h (fp16) + final c ----------------
__global__ __launch_bounds__(256)
void scan_phase2_kernel(const float* __restrict__ g, __half* __restrict__ H,
                        float* __restrict__ out, int layer, int write_h) {
    int idx = blockIdx.x * 256 + threadIdx.x;
    if (idx >= NCH * B_DIM * H_DIM) return;
    int j = idx % H_DIM;
    int b = (idx / H_DIM) % B_DIM;
    int ch = idx / (H_DIM * B_DIM);

    float c = 0.f;
    for (int i = 0; i < ch; i++) {
        size_t o = ((size_t)i * B_DIM + b) * H_DIM + j;
        c = Cc_buf[o] + Pc_buf[o] * c;
    }

    const float* gp = g + (size_t)b * N_OUT + j;
    int t0b = ch * TC;
    for (int t0 = t0b; t0 < t0b + TC; t0 += 4) {
        float zt[4], fs[4], os[4];
#pragma unroll
        for (int u = 0; u < 4; u++) {
            size_t base = (size_t)(t0 + u) * B_DIM * N_OUT;
            zt[u] = gp[base];
            fs[u] = gp[base + H_DIM];
            os[u] = gp[base + 2 * H_DIM];
        }
#pragma unroll
        for (int u = 0; u < 4; u++) {
            c = fmaf(fs[u], zt[u] - c, c);
            if (write_h)
                H[(size_t)((t0 + u) * B_DIM + b) * KPAD + j] = __float2half(os[u] * c);
        }
    }
    if (ch == NCH - 1)
        out[(size_t)b * (L_DIM * H_DIM) + (size_t)layer * H_DIM + j] = c;
}

// ---------------- launch ----------------
extern "C" void kernel_launch(void* const* d_in, const int* in_sizes, int n_in,
                              void* d_out, int out_size) {
    const float* sent = (const float*)d_in[0];
    const float* W0 = (const float*)d_in[2];
    const float* b0 = (const float*)d_in[3];
    const float* W1 = (const float*)d_in[4];
    const float* b1 = (const float*)d_in[5];
    const float* W2 = (const float*)d_in[6];
    const float* b2 = (const float*)d_in[7];
    float* out = (float*)d_out;

    float* g;   cudaGetSymbolAddress((void**)&g, g_buf);
    __half *a0, *a12, *w0h, *w0l, *w1h, *w1l, *w2h, *w2l;
    cudaGetSymbolAddress((void**)&a0, A0_buf);
    cudaGetSymbolAddress((void**)&a12, A12_buf);
    cudaGetSymbolAddress((void**)&w0h, W0h_buf); cudaGetSymbolAddress((void**)&w0l, W0l_buf);
    cudaGetSymbolAddress((void**)&w1h, W1h_buf); cudaGetSymbolAddress((void**)&w1l, W1l_buf);
    cudaGetSymbolAddress((void**)&w2h, W2h_buf); cudaGetSymbolAddress((void**)&w2l, W2l_buf);

    cudaFuncSetAttribute(qrnn_gemm_kernel, cudaFuncAttributeMaxDynamicSharedMemorySize,
                         STAGES * STAGE_BYTES);

    // zero A12 so its K-padding columns (800..831) stay 0 across layers
    cudaMemsetAsync(a12, 0, (size_t)M_DIM * KPAD * sizeof(__half), 0);

    dim3 wblk(32, 8);
    dim3 wgrid0(N_PADROWS / 32, KPAD0 / 32);
    dim3 wgrid12(N_PADROWS / 32, KPAD / 32);
    conv_w_kernel<<<wgrid0, wblk>>>(W0, w0h, w0l, E_DIM, KPAD0);
    conv_w_kernel<<<wgrid12, wblk>>>(W1, w1h, w1l, H_DIM, KPAD);
    conv_w_kernel<<<wgrid12, wblk>>>(W2, w2h, w2l, H_DIM, KPAD);

    {
        size_t n = (size_t)M_DIM * KPAD0;
        conv_sent_kernel<<<(unsigned)((n + 255) / 256), 256>>>(sent);
    }

    dim3 ggrid(N_PADROWS / BN, M_DIM / BM);   // (19, 256)
    size_t smem = STAGES * STAGE_BYTES;
    int scan_total = NCH * B_DIM * H_DIM;
    int scan_blocks = (scan_total + 255) / 256;

    qrnn_gemm_kernel<<<ggrid, 256, smem>>>(a0, w0h, w0l, KPAD0, KPAD0 / BK, b0, g);
    scan_phase1_kernel<<<scan_blocks, 256>>>(g);
    scan_phase2_kernel<<<scan_blocks, 256>>>(g, a12, out, 0, 1);

    qrnn_gemm_kernel<<<ggrid, 256, smem>>>(a12, w1h, w1l, KPAD, KPAD / BK, b1, g);
    scan_phase1_kernel<<<scan_blocks, 256>>>(g);
    scan_phase2_kernel<<<scan_blocks, 256>>>(g, a12, out, 1, 1);

    qrnn_gemm_kernel<<<ggrid, 256, smem>>>(a12, w2h, w2l, KPAD, KPAD / BK, b2, g);
    scan_phase1_kernel<<<scan_blocks, 256>>>(g);
    scan_phase2_kernel<<<scan_blocks, 256>>>(g, a12, out, 2, 0);
}